// round 11
// baseline (speedup 1.0000x reference)
#include <cuda_runtime.h>

#define B_ 16
#define N_ 1024
#define L_ 96

// ---------------- scratch (static device globals; no allocation) ----------------
static __device__ float g_Yt[B_ * L_ * N_];       // Y transposed: [b][k][n]
static __device__ float g_sq[B_ * N_];            // row squared norms
static __device__ float g_dist[B_ * N_ * N_];     // pairwise distances (clamped)
static __device__ int   g_rowmin[B_ * N_];        // min off-diag dist per row (float bits)

// ---------------- kernel 0: init rowmin to +inf ----------------
__global__ void k_init() {
    int i = (blockIdx.x << 8) + threadIdx.x;      // 64 * 256 = 16384 exact
    g_rowmin[i] = 0x7F800000;                      // +inf bits
}

// ---------------- kernel 1: DWT + standardize/abs + Y = Xw * A^T (+ sq, Yt) ----------------
__global__ __launch_bounds__(256) void k_prep(const float* __restrict__ X,
                                              const float* __restrict__ A) {
    __shared__ __align__(16) float As[96 * 100];   // A[k][d], pitch 100 (conflict-free f4)
    __shared__ __align__(16) float Xs[8][96];      // X -> W -> Xw (reused in place)
    __shared__ float Ts[8][48];                    // approx coefficients temp
    __shared__ float Ys[8][96];                    // Y staging

    const int tid  = threadIdx.x;
    const int w    = tid >> 5;
    const int lane = tid & 31;
    const int row0 = blockIdx.x << 3;              // 8 rows per block
    const int row  = row0 + w;

    // stage A into smem (coalesced read, conflict-free write)
    for (int g = tid; g < 96 * 96; g += 256) {
        int k = g / 96, d = g - k * 96;
        As[k * 100 + d] = A[g];
    }

    // load this warp's row of X
    const float* xp = X + row * 96;
    Xs[w][lane]      = xp[lane];
    Xs[w][lane + 32] = xp[lane + 32];
    Xs[w][lane + 64] = xp[lane + 64];
    __syncwarp();

    const float S2 = 1.4142135623730951f;          // fp32(sqrt(2)), divide like reference

    // ---- Haar level 1: 96 -> 48 detail (W[0:48]) + 48 approx (Ts) ----
    {
        float e0 = Xs[w][2 * lane], o0 = Xs[w][2 * lane + 1];
        float e1 = 0.f, o1 = 0.f;
        if (lane < 16) { e1 = Xs[w][2 * (lane + 32)]; o1 = Xs[w][2 * (lane + 32) + 1]; }
        __syncwarp();
        Xs[w][lane] = __fdiv_rn(e0 - o0, S2);
        Ts[w][lane] = __fdiv_rn(e0 + o0, S2);
        if (lane < 16) {
            Xs[w][lane + 32] = __fdiv_rn(e1 - o1, S2);
            Ts[w][lane + 32] = __fdiv_rn(e1 + o1, S2);
        }
        __syncwarp();
    }
    // ---- level 2: 48 -> 24 detail (W[48:72]) + 24 approx ----
    {
        float e = 0.f, o = 0.f;
        if (lane < 24) { e = Ts[w][2 * lane]; o = Ts[w][2 * lane + 1]; }
        __syncwarp();
        if (lane < 24) {
            Xs[w][48 + lane] = __fdiv_rn(e - o, S2);
            Ts[w][lane]      = __fdiv_rn(e + o, S2);
        }
        __syncwarp();
    }
    // ---- level 3: 24 -> 12 detail (W[72:84]) + 12 approx (W[84:96]) ----
    {
        float e = 0.f, o = 0.f;
        if (lane < 12) { e = Ts[w][2 * lane]; o = Ts[w][2 * lane + 1]; }
        __syncwarp();
        if (lane < 12) {
            Xs[w][72 + lane] = __fdiv_rn(e - o, S2);
            Xs[w][84 + lane] = __fdiv_rn(e + o, S2);
        }
        __syncwarp();
    }

    // ---- mean / var / standardized abs ----
    float w0 = Xs[w][lane], w1 = Xs[w][lane + 32], w2 = Xs[w][lane + 64];
    float s = w0 + w1 + w2;
    #pragma unroll
    for (int off = 16; off; off >>= 1) s += __shfl_xor_sync(0xFFFFFFFFu, s, off);
    float mu = __fdiv_rn(s, 96.0f);
    float v0 = w0 - mu, v1 = w1 - mu, v2 = w2 - mu;
    float q = v0 * v0 + v1 * v1 + v2 * v2;
    #pragma unroll
    for (int off = 16; off; off >>= 1) q += __shfl_xor_sync(0xFFFFFFFFu, q, off);
    float var = __fdiv_rn(q, 96.0f);
    float den = __fsqrt_rn(var + 1e-5f);
    Xs[w][lane]      = fabsf(__fdiv_rn(v0, den));
    Xs[w][lane + 32] = fabsf(__fdiv_rn(v1, den));
    Xs[w][lane + 64] = fabsf(__fdiv_rn(v2, den));
    __syncthreads();

    // ---- Y[n,k] = sum_d Xw[n,d] * A[k,d] : 192 threads, thread = (k, 4-row group) ----
    if (tid < 192) {
        const int k  = (tid < 96) ? tid : tid - 96;
        const int r0 = (tid < 96) ? 0 : 4;
        float a0 = 0.f, a1 = 0.f, a2 = 0.f, a3 = 0.f;
        #pragma unroll
        for (int d = 0; d < 96; d += 4) {
            const float4 av = *(const float4*)&As[k * 100 + d];
            const float4 x0 = *(const float4*)&Xs[r0 + 0][d];
            const float4 x1 = *(const float4*)&Xs[r0 + 1][d];
            const float4 x2 = *(const float4*)&Xs[r0 + 2][d];
            const float4 x3 = *(const float4*)&Xs[r0 + 3][d];
            a0 = fmaf(x0.x, av.x, a0); a0 = fmaf(x0.y, av.y, a0);
            a0 = fmaf(x0.z, av.z, a0); a0 = fmaf(x0.w, av.w, a0);
            a1 = fmaf(x1.x, av.x, a1); a1 = fmaf(x1.y, av.y, a1);
            a1 = fmaf(x1.z, av.z, a1); a1 = fmaf(x1.w, av.w, a1);
            a2 = fmaf(x2.x, av.x, a2); a2 = fmaf(x2.y, av.y, a2);
            a2 = fmaf(x2.z, av.z, a2); a2 = fmaf(x2.w, av.w, a2);
            a3 = fmaf(x3.x, av.x, a3); a3 = fmaf(x3.y, av.y, a3);
            a3 = fmaf(x3.z, av.z, a3); a3 = fmaf(x3.w, av.w, a3);
        }
        Ys[r0 + 0][k] = a0; Ys[r0 + 1][k] = a1;
        Ys[r0 + 2][k] = a2; Ys[r0 + 3][k] = a3;
    }
    __syncthreads();

    // ---- sq per row ----
    float y0 = Ys[w][lane], y1 = Ys[w][lane + 32], y2 = Ys[w][lane + 64];
    float qq = y0 * y0 + y1 * y1 + y2 * y2;
    #pragma unroll
    for (int off = 16; off; off >>= 1) qq += __shfl_xor_sync(0xFFFFFFFFu, qq, off);
    if (lane == 0) g_sq[row] = qq;

    // ---- transposed store Yt[b][k][n] (8 consecutive n per k -> full 32B sectors) ----
    const int b  = row0 >> 10;
    const int n0 = row0 & 1023;
    for (int o2 = tid; o2 < 768; o2 += 256) {
        int k = o2 >> 3, r = o2 & 7;
        g_Yt[((b * 96 + k) << 10) + n0 + r] = Ys[r][k];
    }
}

// ---------------- kernel 2: dist = max(sq_i + sq_j - 2*Y_i.Y_j, 0) + row-min ----------------
__global__ __launch_bounds__(256) void k_gram() {
    __shared__ __align__(16) float As[32 * 128];
    __shared__ __align__(16) float Bs[32 * 128];
    __shared__ float sqi[128], sqj[128];
    __shared__ int rmin[128];

    const int tid = threadIdx.x;
    const int b   = blockIdx.z;
    const int Ib  = blockIdx.y << 7;
    const int Jb  = blockIdx.x << 7;

    if (tid < 128) {
        sqi[tid]  = g_sq[(b << 10) + Ib + tid];
        rmin[tid] = 0x7F800000;
    } else {
        sqj[tid - 128] = g_sq[(b << 10) + Jb + (tid - 128)];
    }

    const int ty = tid >> 4, tx = tid & 15;
    float acc[8][8];
    #pragma unroll
    for (int u = 0; u < 8; u++)
        #pragma unroll
        for (int v = 0; v < 8; v++) acc[u][v] = 0.f;

    const float* Yt = g_Yt + b * (96 * 1024);
    for (int kc = 0; kc < 96; kc += 32) {
        __syncthreads();
        #pragma unroll
        for (int s2 = 0; s2 < 4; s2++) {
            int f = tid + (s2 << 8);
            int k = f >> 5, c = (f & 31) << 2;
            const float* gsrc = Yt + ((kc + k) << 10);
            *(float4*)&As[(k << 7) + c] = *(const float4*)&gsrc[Ib + c];
            *(float4*)&Bs[(k << 7) + c] = *(const float4*)&gsrc[Jb + c];
        }
        __syncthreads();
        #pragma unroll 4
        for (int k = 0; k < 32; k++) {
            float av[8], bv[8];
            // split 4+4 micro-tile: stride-4-word f4 loads -> conflict-free LDS.128
            *(float4*)&av[0] = *(const float4*)&As[(k << 7) + (ty << 2)];
            *(float4*)&av[4] = *(const float4*)&As[(k << 7) + 64 + (ty << 2)];
            *(float4*)&bv[0] = *(const float4*)&Bs[(k << 7) + (tx << 2)];
            *(float4*)&bv[4] = *(const float4*)&Bs[(k << 7) + 64 + (tx << 2)];
            #pragma unroll
            for (int u = 0; u < 8; u++)
                #pragma unroll
                for (int v = 0; v < 8; v++)
                    acc[u][v] = fmaf(av[u], bv[v], acc[u][v]);
        }
    }
    __syncthreads();

    #pragma unroll
    for (int u = 0; u < 8; u++) {
        int ru = (u < 4) ? (ty << 2) + u : 64 + (ty << 2) + (u - 4);
        int gi = Ib + ru;
        float si = sqi[ru];
        float dv[8];
        float mn = __int_as_float(0x7F800000);
        #pragma unroll
        for (int v = 0; v < 8; v++) {
            int cv = (v < 4) ? (tx << 2) + v : 64 + (tx << 2) + (v - 4);
            float d = fmaxf(si + sqj[cv] - 2.0f * acc[u][v], 0.0f);
            dv[v] = d;
            if (Jb + cv != gi) mn = fminf(mn, d);   // exclude diagonal from min
        }
        float* dst = g_dist + ((b << 10) + gi) * 1024 + Jb;
        *(float4*)&dst[(tx << 2)]      = make_float4(dv[0], dv[1], dv[2], dv[3]);
        *(float4*)&dst[64 + (tx << 2)] = make_float4(dv[4], dv[5], dv[6], dv[7]);
        atomicMin(&rmin[ru], __float_as_int(mn));   // dist >= 0 -> int order == float order
    }
    __syncthreads();
    if (tid < 128)
        atomicMin(&g_rowmin[(b << 10) + Ib + tid], rmin[tid]);
}

// ---------------- kernel 3: gumbel-argmax epilogue (binary output) ----------------
__global__ __launch_bounds__(256) void k_mask(const float* __restrict__ gum,
                                              float* __restrict__ out) {
    int idx = (blockIdx.x << 8) + threadIdx.x;     // 65536 * 256 = 16M exact
    int m  = idx & 1023;
    int bn = idx >> 10;                             // b*1024 + n
    int n  = bn & 1023;

    float dmin = __int_as_float(g_rowmin[bn]);
    float emax = __frcp_rn(dmin + 1e-5f);           // == max over m of 1/(dist+1e-5)

    float p;
    if (n == m) {
        p = 0.99f;                                   // (p*off + eye)*0.99 on the diagonal
    } else {
        float ed = __frcp_rn(g_dist[idx] + 1e-5f);
        p = __fdiv_rn(ed, emax + 1e-5f) * 0.99f;
    }
    float l0 = logf(p + 1e-10f);
    float l1 = logf(1.0f - p + 1e-10f);
    float2 g = reinterpret_cast<const float2*>(gum)[idx];
    // softmax is monotone; argmax ties -> index 0; sample == hard0 numerically
    out[idx] = (l0 + g.x >= l1 + g.y) ? 1.0f : 0.0f;
}

// ---------------- launch ----------------
extern "C" void kernel_launch(void* const* d_in, const int* in_sizes, int n_in,
                              void* d_out, int out_size) {
    (void)in_sizes; (void)n_in; (void)out_size;
    const float* X   = (const float*)d_in[0];      // [16,1024,96]
    const float* A   = (const float*)d_in[1];      // [96,96]
    const float* gum = (const float*)d_in[2];      // [16,1024,1024,2]
    float* out = (float*)d_out;                    // [16,1,1024,1024]

    k_init<<<64, 256>>>();
    k_prep<<<2048, 256>>>(X, A);
    k_gram<<<dim3(8, 8, 16), 256>>>();
    k_mask<<<65536, 256>>>(gum, out);
}

// round 12
// speedup vs baseline: 1.0054x; 1.0054x over previous
#include <cuda_runtime.h>

#define B_ 16
#define N_ 1024
#define L_ 96

// ---------------- scratch (static device globals; no allocation) ----------------
static __device__ float g_Yt[B_ * L_ * N_];       // Y transposed: [b][k][n]
static __device__ float g_sq[B_ * N_];            // row squared norms
static __device__ float g_dist[B_ * N_ * N_];     // pairwise distances (clamped)
static __device__ int   g_rowmin[B_ * N_];        // min off-diag dist per row (float bits)

// ---------------- kernel 0: init rowmin to +inf ----------------
__global__ void k_init() {
    int i = (blockIdx.x << 8) + threadIdx.x;      // 64 * 256 = 16384 exact
    g_rowmin[i] = 0x7F800000;                      // +inf bits
}

// ---------------- kernel 1: DWT + standardize/abs + Y = Xw * A^T (+ sq, Yt) ----------------
__global__ __launch_bounds__(256) void k_prep(const float* __restrict__ X,
                                              const float* __restrict__ A) {
    __shared__ __align__(16) float As[96 * 100];   // A[k][d], pitch 100 (conflict-free f4)
    __shared__ __align__(16) float Xs[8][96];      // X -> W -> Xw (reused in place)
    __shared__ float Ts[8][48];                    // approx coefficients temp
    __shared__ float Ys[8][96];                    // Y staging

    const int tid  = threadIdx.x;
    const int w    = tid >> 5;
    const int lane = tid & 31;
    const int row0 = blockIdx.x << 3;              // 8 rows per block
    const int row  = row0 + w;

    // stage A into smem (coalesced read, conflict-free write)
    for (int g = tid; g < 96 * 96; g += 256) {
        int k = g / 96, d = g - k * 96;
        As[k * 100 + d] = A[g];
    }

    // load this warp's row of X
    const float* xp = X + row * 96;
    Xs[w][lane]      = xp[lane];
    Xs[w][lane + 32] = xp[lane + 32];
    Xs[w][lane + 64] = xp[lane + 64];
    __syncwarp();

    const float S2 = 1.4142135623730951f;          // fp32(sqrt(2)), divide like reference

    // ---- Haar level 1: 96 -> 48 detail (W[0:48]) + 48 approx (Ts) ----
    {
        float e0 = Xs[w][2 * lane], o0 = Xs[w][2 * lane + 1];
        float e1 = 0.f, o1 = 0.f;
        if (lane < 16) { e1 = Xs[w][2 * (lane + 32)]; o1 = Xs[w][2 * (lane + 32) + 1]; }
        __syncwarp();
        Xs[w][lane] = __fdiv_rn(e0 - o0, S2);
        Ts[w][lane] = __fdiv_rn(e0 + o0, S2);
        if (lane < 16) {
            Xs[w][lane + 32] = __fdiv_rn(e1 - o1, S2);
            Ts[w][lane + 32] = __fdiv_rn(e1 + o1, S2);
        }
        __syncwarp();
    }
    // ---- level 2: 48 -> 24 detail (W[48:72]) + 24 approx ----
    {
        float e = 0.f, o = 0.f;
        if (lane < 24) { e = Ts[w][2 * lane]; o = Ts[w][2 * lane + 1]; }
        __syncwarp();
        if (lane < 24) {
            Xs[w][48 + lane] = __fdiv_rn(e - o, S2);
            Ts[w][lane]      = __fdiv_rn(e + o, S2);
        }
        __syncwarp();
    }
    // ---- level 3: 24 -> 12 detail (W[72:84]) + 12 approx (W[84:96]) ----
    {
        float e = 0.f, o = 0.f;
        if (lane < 12) { e = Ts[w][2 * lane]; o = Ts[w][2 * lane + 1]; }
        __syncwarp();
        if (lane < 12) {
            Xs[w][72 + lane] = __fdiv_rn(e - o, S2);
            Xs[w][84 + lane] = __fdiv_rn(e + o, S2);
        }
        __syncwarp();
    }

    // ---- mean / var / standardized abs ----
    float w0 = Xs[w][lane], w1 = Xs[w][lane + 32], w2 = Xs[w][lane + 64];
    float s = w0 + w1 + w2;
    #pragma unroll
    for (int off = 16; off; off >>= 1) s += __shfl_xor_sync(0xFFFFFFFFu, s, off);
    float mu = __fdiv_rn(s, 96.0f);
    float v0 = w0 - mu, v1 = w1 - mu, v2 = w2 - mu;
    float q = v0 * v0 + v1 * v1 + v2 * v2;
    #pragma unroll
    for (int off = 16; off; off >>= 1) q += __shfl_xor_sync(0xFFFFFFFFu, q, off);
    float var = __fdiv_rn(q, 96.0f);
    float den = __fsqrt_rn(var + 1e-5f);
    Xs[w][lane]      = fabsf(__fdiv_rn(v0, den));
    Xs[w][lane + 32] = fabsf(__fdiv_rn(v1, den));
    Xs[w][lane + 64] = fabsf(__fdiv_rn(v2, den));
    __syncthreads();

    // ---- Y[n,k] = sum_d Xw[n,d] * A[k,d] : 192 threads, thread = (k, 4-row group) ----
    if (tid < 192) {
        const int k  = (tid < 96) ? tid : tid - 96;
        const int r0 = (tid < 96) ? 0 : 4;
        float a0 = 0.f, a1 = 0.f, a2 = 0.f, a3 = 0.f;
        #pragma unroll
        for (int d = 0; d < 96; d += 4) {
            const float4 av = *(const float4*)&As[k * 100 + d];
            const float4 x0 = *(const float4*)&Xs[r0 + 0][d];
            const float4 x1 = *(const float4*)&Xs[r0 + 1][d];
            const float4 x2 = *(const float4*)&Xs[r0 + 2][d];
            const float4 x3 = *(const float4*)&Xs[r0 + 3][d];
            a0 = fmaf(x0.x, av.x, a0); a0 = fmaf(x0.y, av.y, a0);
            a0 = fmaf(x0.z, av.z, a0); a0 = fmaf(x0.w, av.w, a0);
            a1 = fmaf(x1.x, av.x, a1); a1 = fmaf(x1.y, av.y, a1);
            a1 = fmaf(x1.z, av.z, a1); a1 = fmaf(x1.w, av.w, a1);
            a2 = fmaf(x2.x, av.x, a2); a2 = fmaf(x2.y, av.y, a2);
            a2 = fmaf(x2.z, av.z, a2); a2 = fmaf(x2.w, av.w, a2);
            a3 = fmaf(x3.x, av.x, a3); a3 = fmaf(x3.y, av.y, a3);
            a3 = fmaf(x3.z, av.z, a3); a3 = fmaf(x3.w, av.w, a3);
        }
        Ys[r0 + 0][k] = a0; Ys[r0 + 1][k] = a1;
        Ys[r0 + 2][k] = a2; Ys[r0 + 3][k] = a3;
    }
    __syncthreads();

    // ---- sq per row ----
    float y0 = Ys[w][lane], y1 = Ys[w][lane + 32], y2 = Ys[w][lane + 64];
    float qq = y0 * y0 + y1 * y1 + y2 * y2;
    #pragma unroll
    for (int off = 16; off; off >>= 1) qq += __shfl_xor_sync(0xFFFFFFFFu, qq, off);
    if (lane == 0) g_sq[row] = qq;

    // ---- transposed store Yt[b][k][n] (8 consecutive n per k -> full 32B sectors) ----
    const int b  = row0 >> 10;
    const int n0 = row0 & 1023;
    for (int o2 = tid; o2 < 768; o2 += 256) {
        int k = o2 >> 3, r = o2 & 7;
        g_Yt[((b * 96 + k) << 10) + n0 + r] = Ys[r][k];
    }
}

// ---------------- kernel 2: dist = max(sq_i + sq_j - 2*Y_i.Y_j, 0) + row-min ----------------
__global__ __launch_bounds__(256) void k_gram() {
    __shared__ __align__(16) float As[32 * 128];
    __shared__ __align__(16) float Bs[32 * 128];
    __shared__ float sqi[128], sqj[128];
    __shared__ int rmin[128];

    const int tid = threadIdx.x;
    const int b   = blockIdx.z;
    const int Ib  = blockIdx.y << 7;
    const int Jb  = blockIdx.x << 7;

    if (tid < 128) {
        sqi[tid]  = g_sq[(b << 10) + Ib + tid];
        rmin[tid] = 0x7F800000;
    } else {
        sqj[tid - 128] = g_sq[(b << 10) + Jb + (tid - 128)];
    }

    const int ty = tid >> 4, tx = tid & 15;
    float acc[8][8];
    #pragma unroll
    for (int u = 0; u < 8; u++)
        #pragma unroll
        for (int v = 0; v < 8; v++) acc[u][v] = 0.f;

    const float* Yt = g_Yt + b * (96 * 1024);
    for (int kc = 0; kc < 96; kc += 32) {
        __syncthreads();
        #pragma unroll
        for (int s2 = 0; s2 < 4; s2++) {
            int f = tid + (s2 << 8);
            int k = f >> 5, c = (f & 31) << 2;
            const float* gsrc = Yt + ((kc + k) << 10);
            *(float4*)&As[(k << 7) + c] = *(const float4*)&gsrc[Ib + c];
            *(float4*)&Bs[(k << 7) + c] = *(const float4*)&gsrc[Jb + c];
        }
        __syncthreads();
        #pragma unroll 4
        for (int k = 0; k < 32; k++) {
            float av[8], bv[8];
            // split 4+4 micro-tile: stride-4-word f4 loads -> conflict-free LDS.128
            *(float4*)&av[0] = *(const float4*)&As[(k << 7) + (ty << 2)];
            *(float4*)&av[4] = *(const float4*)&As[(k << 7) + 64 + (ty << 2)];
            *(float4*)&bv[0] = *(const float4*)&Bs[(k << 7) + (tx << 2)];
            *(float4*)&bv[4] = *(const float4*)&Bs[(k << 7) + 64 + (tx << 2)];
            #pragma unroll
            for (int u = 0; u < 8; u++)
                #pragma unroll
                for (int v = 0; v < 8; v++)
                    acc[u][v] = fmaf(av[u], bv[v], acc[u][v]);
        }
    }
    __syncthreads();

    #pragma unroll
    for (int u = 0; u < 8; u++) {
        int ru = (u < 4) ? (ty << 2) + u : 64 + (ty << 2) + (u - 4);
        int gi = Ib + ru;
        float si = sqi[ru];
        float dv[8];
        float mn = __int_as_float(0x7F800000);
        #pragma unroll
        for (int v = 0; v < 8; v++) {
            int cv = (v < 4) ? (tx << 2) + v : 64 + (tx << 2) + (v - 4);
            float d = fmaxf(si + sqj[cv] - 2.0f * acc[u][v], 0.0f);
            dv[v] = d;
            if (Jb + cv != gi) mn = fminf(mn, d);   // exclude diagonal from min
        }
        float* dst = g_dist + ((b << 10) + gi) * 1024 + Jb;
        *(float4*)&dst[(tx << 2)]      = make_float4(dv[0], dv[1], dv[2], dv[3]);
        *(float4*)&dst[64 + (tx << 2)] = make_float4(dv[4], dv[5], dv[6], dv[7]);
        atomicMin(&rmin[ru], __float_as_int(mn));   // dist >= 0 -> int order == float order
    }
    __syncthreads();
    if (tid < 128)
        atomicMin(&g_rowmin[(b << 10) + Ib + tid], rmin[tid]);
}

// ---------------- kernel 3: gumbel-argmax epilogue (binary output) ----------------
__global__ __launch_bounds__(256) void k_mask(const float* __restrict__ gum,
                                              float* __restrict__ out) {
    int idx = (blockIdx.x << 8) + threadIdx.x;     // 65536 * 256 = 16M exact
    int m  = idx & 1023;
    int bn = idx >> 10;                             // b*1024 + n
    int n  = bn & 1023;

    float dmin = __int_as_float(g_rowmin[bn]);
    float emax = __frcp_rn(dmin + 1e-5f);           // == max over m of 1/(dist+1e-5)

    float p;
    if (n == m) {
        p = 0.99f;                                   // (p*off + eye)*0.99 on the diagonal
    } else {
        float ed = __frcp_rn(g_dist[idx] + 1e-5f);
        p = __fdiv_rn(ed, emax + 1e-5f) * 0.99f;
    }
    float l0 = logf(p + 1e-10f);
    float l1 = logf(1.0f - p + 1e-10f);
    float2 g = reinterpret_cast<const float2*>(gum)[idx];
    // softmax is monotone; argmax ties -> index 0; sample == hard0 numerically
    out[idx] = (l0 + g.x >= l1 + g.y) ? 1.0f : 0.0f;
}

// ---------------- launch ----------------
extern "C" void kernel_launch(void* const* d_in, const int* in_sizes, int n_in,
                              void* d_out, int out_size) {
    (void)in_sizes; (void)n_in; (void)out_size;
    const float* X   = (const float*)d_in[0];      // [16,1024,96]
    const float* A   = (const float*)d_in[1];      // [96,96]
    const float* gum = (const float*)d_in[2];      // [16,1024,1024,2]
    float* out = (float*)d_out;                    // [16,1,1024,1024]

    k_init<<<64, 256>>>();
    k_prep<<<2048, 256>>>(X, A);
    k_gram<<<dim3(8, 8, 16), 256>>>();
    k_mask<<<65536, 256>>>(gum, out);
}

// round 13
// speedup vs baseline: 1.0073x; 1.0018x over previous
#include <cuda_runtime.h>

#define B_ 16
#define N_ 1024
#define L_ 96

// ---------------- scratch (static device globals; no allocation) ----------------
static __device__ float g_Yt[B_ * L_ * N_];       // Y transposed: [b][k][n]
static __device__ float g_sq[B_ * N_];            // row squared norms
static __device__ float g_dist[B_ * N_ * N_];     // pairwise distances (clamped)
static __device__ int   g_rowmin[B_ * N_];        // min off-diag dist per row (float bits)

// ---------------- kernel 0: init rowmin to +inf ----------------
__global__ void k_init() {
    int i = (blockIdx.x << 8) + threadIdx.x;      // 64 * 256 = 16384 exact
    g_rowmin[i] = 0x7F800000;                      // +inf bits
}

// ---------------- kernel 1: DWT + standardize/abs + Y = Xw * A^T (+ sq, Yt) ----------------
__global__ __launch_bounds__(256) void k_prep(const float* __restrict__ X,
                                              const float* __restrict__ A) {
    __shared__ __align__(16) float As[96 * 100];   // A[k][d], pitch 100 (conflict-free f4)
    __shared__ __align__(16) float Xs[8][96];      // X -> W -> Xw (reused in place)
    __shared__ float Ts[8][48];                    // approx coefficients temp
    __shared__ float Ys[8][96];                    // Y staging

    const int tid  = threadIdx.x;
    const int w    = tid >> 5;
    const int lane = tid & 31;
    const int row0 = blockIdx.x << 3;              // 8 rows per block
    const int row  = row0 + w;

    // stage A into smem (coalesced read, conflict-free write)
    for (int g = tid; g < 96 * 96; g += 256) {
        int k = g / 96, d = g - k * 96;
        As[k * 100 + d] = A[g];
    }

    // load this warp's row of X
    const float* xp = X + row * 96;
    Xs[w][lane]      = xp[lane];
    Xs[w][lane + 32] = xp[lane + 32];
    Xs[w][lane + 64] = xp[lane + 64];
    __syncwarp();

    const float S2 = 1.4142135623730951f;          // fp32(sqrt(2)), divide like reference

    // ---- Haar level 1: 96 -> 48 detail (W[0:48]) + 48 approx (Ts) ----
    {
        float e0 = Xs[w][2 * lane], o0 = Xs[w][2 * lane + 1];
        float e1 = 0.f, o1 = 0.f;
        if (lane < 16) { e1 = Xs[w][2 * (lane + 32)]; o1 = Xs[w][2 * (lane + 32) + 1]; }
        __syncwarp();
        Xs[w][lane] = __fdiv_rn(e0 - o0, S2);
        Ts[w][lane] = __fdiv_rn(e0 + o0, S2);
        if (lane < 16) {
            Xs[w][lane + 32] = __fdiv_rn(e1 - o1, S2);
            Ts[w][lane + 32] = __fdiv_rn(e1 + o1, S2);
        }
        __syncwarp();
    }
    // ---- level 2: 48 -> 24 detail (W[48:72]) + 24 approx ----
    {
        float e = 0.f, o = 0.f;
        if (lane < 24) { e = Ts[w][2 * lane]; o = Ts[w][2 * lane + 1]; }
        __syncwarp();
        if (lane < 24) {
            Xs[w][48 + lane] = __fdiv_rn(e - o, S2);
            Ts[w][lane]      = __fdiv_rn(e + o, S2);
        }
        __syncwarp();
    }
    // ---- level 3: 24 -> 12 detail (W[72:84]) + 12 approx (W[84:96]) ----
    {
        float e = 0.f, o = 0.f;
        if (lane < 12) { e = Ts[w][2 * lane]; o = Ts[w][2 * lane + 1]; }
        __syncwarp();
        if (lane < 12) {
            Xs[w][72 + lane] = __fdiv_rn(e - o, S2);
            Xs[w][84 + lane] = __fdiv_rn(e + o, S2);
        }
        __syncwarp();
    }

    // ---- mean / var / standardized abs ----
    float w0 = Xs[w][lane], w1 = Xs[w][lane + 32], w2 = Xs[w][lane + 64];
    float s = w0 + w1 + w2;
    #pragma unroll
    for (int off = 16; off; off >>= 1) s += __shfl_xor_sync(0xFFFFFFFFu, s, off);
    float mu = __fdiv_rn(s, 96.0f);
    float v0 = w0 - mu, v1 = w1 - mu, v2 = w2 - mu;
    float q = v0 * v0 + v1 * v1 + v2 * v2;
    #pragma unroll
    for (int off = 16; off; off >>= 1) q += __shfl_xor_sync(0xFFFFFFFFu, q, off);
    float var = __fdiv_rn(q, 96.0f);
    float den = __fsqrt_rn(var + 1e-5f);
    Xs[w][lane]      = fabsf(__fdiv_rn(v0, den));
    Xs[w][lane + 32] = fabsf(__fdiv_rn(v1, den));
    Xs[w][lane + 64] = fabsf(__fdiv_rn(v2, den));
    __syncthreads();

    // ---- Y[n,k] = sum_d Xw[n,d] * A[k,d] : 192 threads, thread = (k, 4-row group) ----
    if (tid < 192) {
        const int k  = (tid < 96) ? tid : tid - 96;
        const int r0 = (tid < 96) ? 0 : 4;
        float a0 = 0.f, a1 = 0.f, a2 = 0.f, a3 = 0.f;
        #pragma unroll
        for (int d = 0; d < 96; d += 4) {
            const float4 av = *(const float4*)&As[k * 100 + d];
            const float4 x0 = *(const float4*)&Xs[r0 + 0][d];
            const float4 x1 = *(const float4*)&Xs[r0 + 1][d];
            const float4 x2 = *(const float4*)&Xs[r0 + 2][d];
            const float4 x3 = *(const float4*)&Xs[r0 + 3][d];
            a0 = fmaf(x0.x, av.x, a0); a0 = fmaf(x0.y, av.y, a0);
            a0 = fmaf(x0.z, av.z, a0); a0 = fmaf(x0.w, av.w, a0);
            a1 = fmaf(x1.x, av.x, a1); a1 = fmaf(x1.y, av.y, a1);
            a1 = fmaf(x1.z, av.z, a1); a1 = fmaf(x1.w, av.w, a1);
            a2 = fmaf(x2.x, av.x, a2); a2 = fmaf(x2.y, av.y, a2);
            a2 = fmaf(x2.z, av.z, a2); a2 = fmaf(x2.w, av.w, a2);
            a3 = fmaf(x3.x, av.x, a3); a3 = fmaf(x3.y, av.y, a3);
            a3 = fmaf(x3.z, av.z, a3); a3 = fmaf(x3.w, av.w, a3);
        }
        Ys[r0 + 0][k] = a0; Ys[r0 + 1][k] = a1;
        Ys[r0 + 2][k] = a2; Ys[r0 + 3][k] = a3;
    }
    __syncthreads();

    // ---- sq per row ----
    float y0 = Ys[w][lane], y1 = Ys[w][lane + 32], y2 = Ys[w][lane + 64];
    float qq = y0 * y0 + y1 * y1 + y2 * y2;
    #pragma unroll
    for (int off = 16; off; off >>= 1) qq += __shfl_xor_sync(0xFFFFFFFFu, qq, off);
    if (lane == 0) g_sq[row] = qq;

    // ---- transposed store Yt[b][k][n] (8 consecutive n per k -> full 32B sectors) ----
    const int b  = row0 >> 10;
    const int n0 = row0 & 1023;
    for (int o2 = tid; o2 < 768; o2 += 256) {
        int k = o2 >> 3, r = o2 & 7;
        g_Yt[((b * 96 + k) << 10) + n0 + r] = Ys[r][k];
    }
}

// ---------------- kernel 2: dist = max(sq_i + sq_j - 2*Y_i.Y_j, 0) + row-min ----------------
__global__ __launch_bounds__(256) void k_gram() {
    __shared__ __align__(16) float As[32 * 128];
    __shared__ __align__(16) float Bs[32 * 128];
    __shared__ float sqi[128], sqj[128];
    __shared__ int rmin[128];

    const int tid = threadIdx.x;
    const int b   = blockIdx.z;
    const int Ib  = blockIdx.y << 7;
    const int Jb  = blockIdx.x << 7;

    if (tid < 128) {
        sqi[tid]  = g_sq[(b << 10) + Ib + tid];
        rmin[tid] = 0x7F800000;
    } else {
        sqj[tid - 128] = g_sq[(b << 10) + Jb + (tid - 128)];
    }

    const int ty = tid >> 4, tx = tid & 15;
    float acc[8][8];
    #pragma unroll
    for (int u = 0; u < 8; u++)
        #pragma unroll
        for (int v = 0; v < 8; v++) acc[u][v] = 0.f;

    const float* Yt = g_Yt + b * (96 * 1024);
    for (int kc = 0; kc < 96; kc += 32) {
        __syncthreads();
        #pragma unroll
        for (int s2 = 0; s2 < 4; s2++) {
            int f = tid + (s2 << 8);
            int k = f >> 5, c = (f & 31) << 2;
            const float* gsrc = Yt + ((kc + k) << 10);
            *(float4*)&As[(k << 7) + c] = *(const float4*)&gsrc[Ib + c];
            *(float4*)&Bs[(k << 7) + c] = *(const float4*)&gsrc[Jb + c];
        }
        __syncthreads();
        #pragma unroll 4
        for (int k = 0; k < 32; k++) {
            float av[8], bv[8];
            // split 4+4 micro-tile: stride-4-word f4 loads -> conflict-free LDS.128
            *(float4*)&av[0] = *(const float4*)&As[(k << 7) + (ty << 2)];
            *(float4*)&av[4] = *(const float4*)&As[(k << 7) + 64 + (ty << 2)];
            *(float4*)&bv[0] = *(const float4*)&Bs[(k << 7) + (tx << 2)];
            *(float4*)&bv[4] = *(const float4*)&Bs[(k << 7) + 64 + (tx << 2)];
            #pragma unroll
            for (int u = 0; u < 8; u++)
                #pragma unroll
                for (int v = 0; v < 8; v++)
                    acc[u][v] = fmaf(av[u], bv[v], acc[u][v]);
        }
    }
    __syncthreads();

    #pragma unroll
    for (int u = 0; u < 8; u++) {
        int ru = (u < 4) ? (ty << 2) + u : 64 + (ty << 2) + (u - 4);
        int gi = Ib + ru;
        float si = sqi[ru];
        float dv[8];
        float mn = __int_as_float(0x7F800000);
        #pragma unroll
        for (int v = 0; v < 8; v++) {
            int cv = (v < 4) ? (tx << 2) + v : 64 + (tx << 2) + (v - 4);
            float d = fmaxf(si + sqj[cv] - 2.0f * acc[u][v], 0.0f);
            dv[v] = d;
            if (Jb + cv != gi) mn = fminf(mn, d);   // exclude diagonal from min
        }
        float* dst = g_dist + ((b << 10) + gi) * 1024 + Jb;
        *(float4*)&dst[(tx << 2)]      = make_float4(dv[0], dv[1], dv[2], dv[3]);
        *(float4*)&dst[64 + (tx << 2)] = make_float4(dv[4], dv[5], dv[6], dv[7]);
        atomicMin(&rmin[ru], __float_as_int(mn));   // dist >= 0 -> int order == float order
    }
    __syncthreads();
    if (tid < 128)
        atomicMin(&g_rowmin[(b << 10) + Ib + tid], rmin[tid]);
}

// ---------------- kernel 3: gumbel-argmax epilogue (binary output) ----------------
__global__ __launch_bounds__(256) void k_mask(const float* __restrict__ gum,
                                              float* __restrict__ out) {
    int idx = (blockIdx.x << 8) + threadIdx.x;     // 65536 * 256 = 16M exact
    int m  = idx & 1023;
    int bn = idx >> 10;                             // b*1024 + n
    int n  = bn & 1023;

    float dmin = __int_as_float(g_rowmin[bn]);
    float emax = __frcp_rn(dmin + 1e-5f);           // == max over m of 1/(dist+1e-5)

    float p;
    if (n == m) {
        p = 0.99f;                                   // (p*off + eye)*0.99 on the diagonal
    } else {
        float ed = __frcp_rn(g_dist[idx] + 1e-5f);
        p = __fdiv_rn(ed, emax + 1e-5f) * 0.99f;
    }
    float l0 = logf(p + 1e-10f);
    float l1 = logf(1.0f - p + 1e-10f);
    float2 g = reinterpret_cast<const float2*>(gum)[idx];
    // softmax is monotone; argmax ties -> index 0; sample == hard0 numerically
    out[idx] = (l0 + g.x >= l1 + g.y) ? 1.0f : 0.0f;
}

// ---------------- launch ----------------
extern "C" void kernel_launch(void* const* d_in, const int* in_sizes, int n_in,
                              void* d_out, int out_size) {
    (void)in_sizes; (void)n_in; (void)out_size;
    const float* X   = (const float*)d_in[0];      // [16,1024,96]
    const float* A   = (const float*)d_in[1];      // [96,96]
    const float* gum = (const float*)d_in[2];      // [16,1024,1024,2]
    float* out = (float*)d_out;                    // [16,1,1024,1024]

    k_init<<<64, 256>>>();
    k_prep<<<2048, 256>>>(X, A);
    k_gram<<<dim3(8, 8, 16), 256>>>();
    k_mask<<<65536, 256>>>(gum, out);
}